// round 1
// baseline (speedup 1.0000x reference)
#include <cuda_runtime.h>
#include <math.h>

#define BATCH   2
#define SEQ     2048
#define DIM     2048
#define NHEADS  16
#define HD      128
#define INTER   8192
#define MROWS   (BATCH*SEQ)      /* 4096 */
#define EPSF    1e-6f
#define NEGF    -1e9f

// ---------------- scratch (device globals: allocation-free) ----------------
__device__ float g_hn[(size_t)MROWS * DIM];
__device__ float g_q [(size_t)MROWS * DIM];
__device__ float g_k [(size_t)MROWS * DIM];
__device__ float g_v [(size_t)MROWS * DIM];
__device__ float g_ao[(size_t)MROWS * DIM];
__device__ float g_h [(size_t)MROWS * DIM];
__device__ float g_scores[(size_t)BATCH * NHEADS * SEQ * SEQ];   // 537 MB
__device__ float g_gate[(size_t)MROWS * INTER];
__device__ float g_up  [(size_t)MROWS * INTER];

// ---------------- RMSNorm: one block per row of DIM=2048 ----------------
__global__ void rmsnorm_kernel(const float* __restrict__ x,
                               const float* __restrict__ w,
                               float* __restrict__ out) {
    int row = blockIdx.x;
    int t = threadIdx.x;                    // 256 threads
    const float4* xr = (const float4*)(x + (size_t)row * DIM);
    const float4* wr = (const float4*)w;
    float4 a = xr[t];
    float4 b = xr[t + 256];
    float s = a.x*a.x + a.y*a.y + a.z*a.z + a.w*a.w
            + b.x*b.x + b.y*b.y + b.z*b.z + b.w*b.w;
    __shared__ float red[256];
    red[t] = s;
    __syncthreads();
    for (int off = 128; off > 0; off >>= 1) {
        if (t < off) red[t] += red[t + off];
        __syncthreads();
    }
    float inv = rsqrtf(red[0] * (1.0f / DIM) + EPSF);
    float4 wa = wr[t], wb = wr[t + 256];
    float4 oa, ob;
    oa.x = a.x * inv * wa.x; oa.y = a.y * inv * wa.y;
    oa.z = a.z * inv * wa.z; oa.w = a.w * inv * wa.w;
    ob.x = b.x * inv * wb.x; ob.y = b.y * inv * wb.y;
    ob.z = b.z * inv * wb.z; ob.w = b.w * inv * wb.w;
    float4* orow = (float4*)(out + (size_t)row * DIM);
    orow[t] = oa;
    orow[t + 256] = ob;
}

// ---------------- SGEMM: C[M,N] = A[M,K] @ B[K,N] (+res), row-major ----------------
// 128x128 tile, BK=8, 256 threads, 8x8 per thread
__global__ void sgemm_kernel(const float* __restrict__ A,
                             const float* __restrict__ Bm,
                             const float* __restrict__ res,
                             float* __restrict__ C,
                             int M, int N, int K, int addres) {
    __shared__ __align__(16) float As[8][128];
    __shared__ __align__(16) float Bs[8][128];
    int bx = blockIdx.x, by = blockIdx.y;
    int t = threadIdx.x;
    int ar = t >> 1, ac = (t & 1) * 4;      // A tile loader: 128 rows x 8 cols
    int br = t >> 5, bc = (t & 31) * 4;     // B tile loader: 8 rows x 128 cols
    int ty = t >> 4, tx = t & 15;
    const float* Ap = A + (size_t)(by * 128 + ar) * K + ac;
    const float* Bp = Bm + (size_t)br * N + bx * 128 + bc;
    float acc[8][8];
    #pragma unroll
    for (int i = 0; i < 8; i++)
        #pragma unroll
        for (int j = 0; j < 8; j++) acc[i][j] = 0.f;

    for (int k0 = 0; k0 < K; k0 += 8) {
        float4 av = *(const float4*)Ap;
        As[ac + 0][ar] = av.x; As[ac + 1][ar] = av.y;
        As[ac + 2][ar] = av.z; As[ac + 3][ar] = av.w;
        *(float4*)&Bs[br][bc] = *(const float4*)Bp;
        __syncthreads();
        #pragma unroll
        for (int kk = 0; kk < 8; kk++) {
            float af[8], bf[8];
            *(float4*)&af[0] = *(const float4*)&As[kk][ty * 8];
            *(float4*)&af[4] = *(const float4*)&As[kk][ty * 8 + 4];
            *(float4*)&bf[0] = *(const float4*)&Bs[kk][tx * 8];
            *(float4*)&bf[4] = *(const float4*)&Bs[kk][tx * 8 + 4];
            #pragma unroll
            for (int i = 0; i < 8; i++)
                #pragma unroll
                for (int j = 0; j < 8; j++)
                    acc[i][j] += af[i] * bf[j];
        }
        __syncthreads();
        Ap += 8;
        Bp += (size_t)8 * N;
    }
    int row0 = by * 128 + ty * 8;
    int col0 = bx * 128 + tx * 8;
    #pragma unroll
    for (int i = 0; i < 8; i++) {
        #pragma unroll
        for (int j = 0; j < 8; j++) {
            size_t idx = (size_t)(row0 + i) * N + col0 + j;
            float v = acc[i][j];
            if (addres) v += res[idx];
            C[idx] = v;
        }
    }
}

// ---------------- scores: S[bh][i][j] = (Q_h[i]·K_h[j]) * scale + mask[i][j] ----------------
// 64x64 tile per block over d=128, skip fully-masked tiles
__global__ void scores_kernel(const float* __restrict__ q,
                              const float* __restrict__ k,
                              const float* __restrict__ mask,
                              float* __restrict__ scores) {
    int bh = blockIdx.z;
    int b = bh >> 4, h = bh & 15;
    int i0 = blockIdx.y * 64, j0 = blockIdx.x * 64;
    float* out = scores + (size_t)bh * SEQ * SEQ;
    int t = threadIdx.x;                    // 256 threads
    if (j0 > i0 + 63) {                     // fully masked block
        for (int e = t; e < 64 * 64; e += 256)
            out[(size_t)(i0 + (e >> 6)) * SEQ + j0 + (e & 63)] = NEGF;
        return;
    }
    __shared__ __align__(16) float Qs[16][64];
    __shared__ __align__(16) float Ks[16][64];
    const float* qb = q + (size_t)(b * SEQ + i0) * DIM + h * HD;
    const float* kb = k + (size_t)(b * SEQ + j0) * DIM + h * HD;
    int lr = t >> 2;            // 0..63
    int lc = (t & 3) * 4;       // 0,4,8,12
    int ty = t >> 4, tx = t & 15;
    float acc[4][4];
    #pragma unroll
    for (int i = 0; i < 4; i++)
        #pragma unroll
        for (int j = 0; j < 4; j++) acc[i][j] = 0.f;

    for (int d0 = 0; d0 < HD; d0 += 16) {
        float4 qa = *(const float4*)(qb + (size_t)lr * DIM + d0 + lc);
        float4 ka = *(const float4*)(kb + (size_t)lr * DIM + d0 + lc);
        Qs[lc + 0][lr] = qa.x; Qs[lc + 1][lr] = qa.y;
        Qs[lc + 2][lr] = qa.z; Qs[lc + 3][lr] = qa.w;
        Ks[lc + 0][lr] = ka.x; Ks[lc + 1][lr] = ka.y;
        Ks[lc + 2][lr] = ka.z; Ks[lc + 3][lr] = ka.w;
        __syncthreads();
        #pragma unroll
        for (int d = 0; d < 16; d++) {
            float qr[4], kr[4];
            *(float4*)qr = *(const float4*)&Qs[d][ty * 4];
            *(float4*)kr = *(const float4*)&Ks[d][tx * 4];
            #pragma unroll
            for (int i = 0; i < 4; i++)
                #pragma unroll
                for (int j = 0; j < 4; j++)
                    acc[i][j] += qr[i] * kr[j];
        }
        __syncthreads();
    }
    const float scale = 0.08838834764831845f;   // 1/sqrt(128)
    #pragma unroll
    for (int i = 0; i < 4; i++) {
        int gi = i0 + ty * 4 + i;
        #pragma unroll
        for (int j = 0; j < 4; j++) {
            int gj = j0 + tx * 4 + j;
            out[(size_t)gi * SEQ + gj] = acc[i][j] * scale + mask[(size_t)gi * SEQ + gj];
        }
    }
}

// ---------------- softmax over each row of 2048 (in place) ----------------
__global__ void softmax_kernel(float* __restrict__ scores) {
    size_t row = blockIdx.x;
    float4* p = (float4*)(scores + row * (size_t)SEQ);
    int t = threadIdx.x;                    // 128 threads, 16 elems each
    float v[16];
    float m = -3.4e38f;
    #pragma unroll
    for (int i = 0; i < 4; i++) {
        float4 f = p[t + i * 128];
        v[i*4+0] = f.x; v[i*4+1] = f.y; v[i*4+2] = f.z; v[i*4+3] = f.w;
        m = fmaxf(m, fmaxf(fmaxf(f.x, f.y), fmaxf(f.z, f.w)));
    }
    __shared__ float red[128];
    red[t] = m;
    __syncthreads();
    for (int off = 64; off > 0; off >>= 1) {
        if (t < off) red[t] = fmaxf(red[t], red[t + off]);
        __syncthreads();
    }
    float rm = red[0];
    __syncthreads();
    float s = 0.f;
    #pragma unroll
    for (int i = 0; i < 16; i++) {
        v[i] = expf(v[i] - rm);             // masked entries underflow to exactly 0
        s += v[i];
    }
    red[t] = s;
    __syncthreads();
    for (int off = 64; off > 0; off >>= 1) {
        if (t < off) red[t] += red[t + off];
        __syncthreads();
    }
    float inv = 1.0f / red[0];
    #pragma unroll
    for (int i = 0; i < 4; i++) {
        float4 f;
        f.x = v[i*4+0] * inv; f.y = v[i*4+1] * inv;
        f.z = v[i*4+2] * inv; f.w = v[i*4+3] * inv;
        p[t + i * 128] = f;
    }
}

// ---------------- AV: out_h[i,d] = sum_j P[i,j] * V_h[j,d], causal-truncated ----------------
// 128x128 tile (N=HD=128 exactly), BK=8, 256 threads, 8x8
__global__ void av_kernel(const float* __restrict__ probs,
                          const float* __restrict__ v,
                          float* __restrict__ out) {
    int bh = blockIdx.z;
    int b = bh >> 4, h = bh & 15;
    int i0 = blockIdx.y * 128;
    const float* A  = probs + (size_t)bh * SEQ * SEQ;
    const float* Bv = v + (size_t)(b * SEQ) * DIM + h * HD;
    float* C        = out + (size_t)(b * SEQ + i0) * DIM + h * HD;
    __shared__ __align__(16) float As[8][128];
    __shared__ __align__(16) float Bs[8][128];
    int t = threadIdx.x;
    int ar = t >> 1, ac = (t & 1) * 4;
    int br = t >> 5, bc = (t & 31) * 4;
    int ty = t >> 4, tx = t & 15;
    float acc[8][8];
    #pragma unroll
    for (int i = 0; i < 8; i++)
        #pragma unroll
        for (int j = 0; j < 8; j++) acc[i][j] = 0.f;

    int kend = i0 + 128;                    // probs are exactly 0 beyond the causal bound
    for (int k0 = 0; k0 < kend; k0 += 8) {
        float4 av = *(const float4*)(A + (size_t)(i0 + ar) * SEQ + k0 + ac);
        As[ac + 0][ar] = av.x; As[ac + 1][ar] = av.y;
        As[ac + 2][ar] = av.z; As[ac + 3][ar] = av.w;
        *(float4*)&Bs[br][bc] = *(const float4*)(Bv + (size_t)(k0 + br) * DIM + bc);
        __syncthreads();
        #pragma unroll
        for (int kk = 0; kk < 8; kk++) {
            float af[8], bf[8];
            *(float4*)&af[0] = *(const float4*)&As[kk][ty * 8];
            *(float4*)&af[4] = *(const float4*)&As[kk][ty * 8 + 4];
            *(float4*)&bf[0] = *(const float4*)&Bs[kk][tx * 8];
            *(float4*)&bf[4] = *(const float4*)&Bs[kk][tx * 8 + 4];
            #pragma unroll
            for (int i = 0; i < 8; i++)
                #pragma unroll
                for (int j = 0; j < 8; j++)
                    acc[i][j] += af[i] * bf[j];
        }
        __syncthreads();
    }
    #pragma unroll
    for (int i = 0; i < 8; i++)
        #pragma unroll
        for (int j = 0; j < 8; j++)
            C[(size_t)(ty * 8 + i) * DIM + tx * 8 + j] = acc[i][j];
}

// ---------------- SiLU(gate) * up, in place into gate ----------------
__global__ void silu_mul_kernel(float* __restrict__ g, const float* __restrict__ u) {
    size_t i = (size_t)blockIdx.x * blockDim.x + threadIdx.x;  // float4 index
    float4 gv = ((const float4*)g)[i];
    float4 uv = ((const float4*)u)[i];
    float4 o;
    o.x = gv.x / (1.f + expf(-gv.x)) * uv.x;
    o.y = gv.y / (1.f + expf(-gv.y)) * uv.y;
    o.z = gv.z / (1.f + expf(-gv.z)) * uv.z;
    o.w = gv.w / (1.f + expf(-gv.w)) * uv.w;
    ((float4*)g)[i] = o;
}

// ---------------- launch ----------------
extern "C" void kernel_launch(void* const* d_in, const int* in_sizes, int n_in,
                              void* d_out, int out_size) {
    const float* x           = (const float*)d_in[0];
    const float* mask        = (const float*)d_in[1];
    const float* w_attn_norm = (const float*)d_in[2];
    const float* wq          = (const float*)d_in[3];
    const float* wk          = (const float*)d_in[4];
    const float* wv          = (const float*)d_in[5];
    const float* wo          = (const float*)d_in[6];
    const float* w_ffn_norm  = (const float*)d_in[7];
    const float* wg          = (const float*)d_in[8];
    const float* wu          = (const float*)d_in[9];
    const float* wd          = (const float*)d_in[10];
    float* out = (float*)d_out;

    float *hn, *q, *k, *v, *ao, *h, *sc, *gate, *up;
    cudaGetSymbolAddress((void**)&hn,   g_hn);
    cudaGetSymbolAddress((void**)&q,    g_q);
    cudaGetSymbolAddress((void**)&k,    g_k);
    cudaGetSymbolAddress((void**)&v,    g_v);
    cudaGetSymbolAddress((void**)&ao,   g_ao);
    cudaGetSymbolAddress((void**)&h,    g_h);
    cudaGetSymbolAddress((void**)&sc,   g_scores);
    cudaGetSymbolAddress((void**)&gate, g_gate);
    cudaGetSymbolAddress((void**)&up,   g_up);

    // attn pre-norm
    rmsnorm_kernel<<<MROWS, 256>>>(x, w_attn_norm, hn);
    // QKV projections
    dim3 gqkv(DIM / 128, MROWS / 128);
    sgemm_kernel<<<gqkv, 256>>>(hn, wq, nullptr, q, MROWS, DIM, DIM, 0);
    sgemm_kernel<<<gqkv, 256>>>(hn, wk, nullptr, k, MROWS, DIM, DIM, 0);
    sgemm_kernel<<<gqkv, 256>>>(hn, wv, nullptr, v, MROWS, DIM, DIM, 0);
    // attention
    scores_kernel<<<dim3(SEQ / 64, SEQ / 64, BATCH * NHEADS), 256>>>(q, k, mask, sc);
    softmax_kernel<<<BATCH * NHEADS * SEQ, 128>>>(sc);
    av_kernel<<<dim3(1, SEQ / 128, BATCH * NHEADS), 256>>>(sc, v, ao);
    // O proj + residual -> h
    sgemm_kernel<<<gqkv, 256>>>(ao, wo, x, h, MROWS, DIM, DIM, 1);
    // ffn pre-norm
    rmsnorm_kernel<<<MROWS, 256>>>(h, w_ffn_norm, hn);
    // gate / up
    dim3 ggu(INTER / 128, MROWS / 128);
    sgemm_kernel<<<ggu, 256>>>(hn, wg, nullptr, gate, MROWS, INTER, DIM, 0);
    sgemm_kernel<<<ggu, 256>>>(hn, wu, nullptr, up,   MROWS, INTER, DIM, 0);
    // silu * up
    silu_mul_kernel<<<((size_t)MROWS * INTER / 4) / 256, 256>>>(gate, up);
    // down proj + residual -> out
    sgemm_kernel<<<gqkv, 256>>>(gate, wd, h, out, MROWS, DIM, INTER, 1);
}

// round 2
// speedup vs baseline: 1.0006x; 1.0006x over previous
#include <cuda_runtime.h>
#include <math.h>

#define BATCH   2
#define SEQ     2048
#define DIM     2048
#define NHEADS  16
#define HD      128
#define INTER   8192
#define MROWS   (BATCH*SEQ)      /* 4096 */
#define EPSF    1e-6f
#define NEGF    -1e9f

// ---------------- scratch (device globals: allocation-free) ----------------
__device__ float g_hn[(size_t)MROWS * DIM];
__device__ float g_q [(size_t)MROWS * DIM];
__device__ float g_k [(size_t)MROWS * DIM];
__device__ float g_v [(size_t)MROWS * DIM];
__device__ float g_ao[(size_t)MROWS * DIM];
__device__ float g_h [(size_t)MROWS * DIM];
__device__ float g_scores[(size_t)BATCH * NHEADS * SEQ * SEQ];   // 537 MB
__device__ float g_gate[(size_t)MROWS * INTER];
__device__ float g_up  [(size_t)MROWS * INTER];

// ---------------- RMSNorm: one block per row of DIM=2048 ----------------
__global__ void rmsnorm_kernel(const float* __restrict__ x,
                               const float* __restrict__ w,
                               float* __restrict__ out) {
    int row = blockIdx.x;
    int t = threadIdx.x;                    // 256 threads
    const float4* xr = (const float4*)(x + (size_t)row * DIM);
    const float4* wr = (const float4*)w;
    float4 a = xr[t];
    float4 b = xr[t + 256];
    float s = a.x*a.x + a.y*a.y + a.z*a.z + a.w*a.w
            + b.x*b.x + b.y*b.y + b.z*b.z + b.w*b.w;
    __shared__ float red[256];
    red[t] = s;
    __syncthreads();
    for (int off = 128; off > 0; off >>= 1) {
        if (t < off) red[t] += red[t + off];
        __syncthreads();
    }
    float inv = rsqrtf(red[0] * (1.0f / DIM) + EPSF);
    float4 wa = wr[t], wb = wr[t + 256];
    float4 oa, ob;
    oa.x = a.x * inv * wa.x; oa.y = a.y * inv * wa.y;
    oa.z = a.z * inv * wa.z; oa.w = a.w * inv * wa.w;
    ob.x = b.x * inv * wb.x; ob.y = b.y * inv * wb.y;
    ob.z = b.z * inv * wb.z; ob.w = b.w * inv * wb.w;
    float4* orow = (float4*)(out + (size_t)row * DIM);
    orow[t] = oa;
    orow[t + 256] = ob;
}

// ---------------- SGEMM: C[M,N] = A[M,K] @ B[K,N] (+res), row-major ----------------
// 128x128 tile, BK=8, 256 threads, 8x8 per thread
__global__ void sgemm_kernel(const float* __restrict__ A,
                             const float* __restrict__ Bm,
                             const float* __restrict__ res,
                             float* __restrict__ C,
                             int M, int N, int K, int addres) {
    __shared__ __align__(16) float As[8][128];
    __shared__ __align__(16) float Bs[8][128];
    int bx = blockIdx.x, by = blockIdx.y;
    int t = threadIdx.x;
    int ar = t >> 1, ac = (t & 1) * 4;      // A tile loader: 128 rows x 8 cols
    int br = t >> 5, bc = (t & 31) * 4;     // B tile loader: 8 rows x 128 cols
    int ty = t >> 4, tx = t & 15;
    const float* Ap = A + (size_t)(by * 128 + ar) * K + ac;
    const float* Bp = Bm + (size_t)br * N + bx * 128 + bc;
    float acc[8][8];
    #pragma unroll
    for (int i = 0; i < 8; i++)
        #pragma unroll
        for (int j = 0; j < 8; j++) acc[i][j] = 0.f;

    for (int k0 = 0; k0 < K; k0 += 8) {
        float4 av = *(const float4*)Ap;
        As[ac + 0][ar] = av.x; As[ac + 1][ar] = av.y;
        As[ac + 2][ar] = av.z; As[ac + 3][ar] = av.w;
        *(float4*)&Bs[br][bc] = *(const float4*)Bp;
        __syncthreads();
        #pragma unroll
        for (int kk = 0; kk < 8; kk++) {
            float af[8], bf[8];
            *(float4*)&af[0] = *(const float4*)&As[kk][ty * 8];
            *(float4*)&af[4] = *(const float4*)&As[kk][ty * 8 + 4];
            *(float4*)&bf[0] = *(const float4*)&Bs[kk][tx * 8];
            *(float4*)&bf[4] = *(const float4*)&Bs[kk][tx * 8 + 4];
            #pragma unroll
            for (int i = 0; i < 8; i++)
                #pragma unroll
                for (int j = 0; j < 8; j++)
                    acc[i][j] += af[i] * bf[j];
        }
        __syncthreads();
        Ap += 8;
        Bp += (size_t)8 * N;
    }
    int row0 = by * 128 + ty * 8;
    int col0 = bx * 128 + tx * 8;
    #pragma unroll
    for (int i = 0; i < 8; i++) {
        #pragma unroll
        for (int j = 0; j < 8; j++) {
            size_t idx = (size_t)(row0 + i) * N + col0 + j;
            float v = acc[i][j];
            if (addres) v += res[idx];
            C[idx] = v;
        }
    }
}

// ---------------- scores: S[bh][i][j] = (Q_h[i]·K_h[j]) * scale + mask[i][j] ----------------
// 64x64 tile per block over d=128, skip fully-masked tiles
__global__ void scores_kernel(const float* __restrict__ q,
                              const float* __restrict__ k,
                              const float* __restrict__ mask,
                              float* __restrict__ scores) {
    int bh = blockIdx.z;
    int b = bh >> 4, h = bh & 15;
    int i0 = blockIdx.y * 64, j0 = blockIdx.x * 64;
    float* out = scores + (size_t)bh * SEQ * SEQ;
    int t = threadIdx.x;                    // 256 threads
    if (j0 > i0 + 63) {                     // fully masked block
        for (int e = t; e < 64 * 64; e += 256)
            out[(size_t)(i0 + (e >> 6)) * SEQ + j0 + (e & 63)] = NEGF;
        return;
    }
    __shared__ __align__(16) float Qs[16][64];
    __shared__ __align__(16) float Ks[16][64];
    const float* qb = q + (size_t)(b * SEQ + i0) * DIM + h * HD;
    const float* kb = k + (size_t)(b * SEQ + j0) * DIM + h * HD;
    int lr = t >> 2;            // 0..63
    int lc = (t & 3) * 4;       // 0,4,8,12
    int ty = t >> 4, tx = t & 15;
    float acc[4][4];
    #pragma unroll
    for (int i = 0; i < 4; i++)
        #pragma unroll
        for (int j = 0; j < 4; j++) acc[i][j] = 0.f;

    for (int d0 = 0; d0 < HD; d0 += 16) {
        float4 qa = *(const float4*)(qb + (size_t)lr * DIM + d0 + lc);
        float4 ka = *(const float4*)(kb + (size_t)lr * DIM + d0 + lc);
        Qs[lc + 0][lr] = qa.x; Qs[lc + 1][lr] = qa.y;
        Qs[lc + 2][lr] = qa.z; Qs[lc + 3][lr] = qa.w;
        Ks[lc + 0][lr] = ka.x; Ks[lc + 1][lr] = ka.y;
        Ks[lc + 2][lr] = ka.z; Ks[lc + 3][lr] = ka.w;
        __syncthreads();
        #pragma unroll
        for (int d = 0; d < 16; d++) {
            float qr[4], kr[4];
            *(float4*)qr = *(const float4*)&Qs[d][ty * 4];
            *(float4*)kr = *(const float4*)&Ks[d][tx * 4];
            #pragma unroll
            for (int i = 0; i < 4; i++)
                #pragma unroll
                for (int j = 0; j < 4; j++)
                    acc[i][j] += qr[i] * kr[j];
        }
        __syncthreads();
    }
    const float scale = 0.08838834764831845f;   // 1/sqrt(128)
    #pragma unroll
    for (int i = 0; i < 4; i++) {
        int gi = i0 + ty * 4 + i;
        #pragma unroll
        for (int j = 0; j < 4; j++) {
            int gj = j0 + tx * 4 + j;
            out[(size_t)gi * SEQ + gj] = acc[i][j] * scale + mask[(size_t)gi * SEQ + gj];
        }
    }
}

// ---------------- softmax over each row of 2048 (in place) ----------------
__global__ void softmax_kernel(float* __restrict__ scores) {
    size_t row = blockIdx.x;
    float4* p = (float4*)(scores + row * (size_t)SEQ);
    int t = threadIdx.x;                    // 128 threads, 16 elems each
    float v[16];
    float m = -3.4e38f;
    #pragma unroll
    for (int i = 0; i < 4; i++) {
        float4 f = p[t + i * 128];
        v[i*4+0] = f.x; v[i*4+1] = f.y; v[i*4+2] = f.z; v[i*4+3] = f.w;
        m = fmaxf(m, fmaxf(fmaxf(f.x, f.y), fmaxf(f.z, f.w)));
    }
    __shared__ float red[128];
    red[t] = m;
    __syncthreads();
    for (int off = 64; off > 0; off >>= 1) {
        if (t < off) red[t] = fmaxf(red[t], red[t + off]);
        __syncthreads();
    }
    float rm = red[0];
    __syncthreads();
    float s = 0.f;
    #pragma unroll
    for (int i = 0; i < 16; i++) {
        v[i] = expf(v[i] - rm);             // masked entries underflow to exactly 0
        s += v[i];
    }
    red[t] = s;
    __syncthreads();
    for (int off = 64; off > 0; off >>= 1) {
        if (t < off) red[t] += red[t + off];
        __syncthreads();
    }
    float inv = 1.0f / red[0];
    #pragma unroll
    for (int i = 0; i < 4; i++) {
        float4 f;
        f.x = v[i*4+0] * inv; f.y = v[i*4+1] * inv;
        f.z = v[i*4+2] * inv; f.w = v[i*4+3] * inv;
        p[t + i * 128] = f;
    }
}

// ---------------- AV: out_h[i,d] = sum_j P[i,j] * V_h[j,d], causal-truncated ----------------
// 128x128 tile (N=HD=128 exactly), BK=8, 256 threads, 8x8
__global__ void av_kernel(const float* __restrict__ probs,
                          const float* __restrict__ v,
                          float* __restrict__ out) {
    int bh = blockIdx.z;
    int b = bh >> 4, h = bh & 15;
    int i0 = blockIdx.y * 128;
    const float* A  = probs + (size_t)bh * SEQ * SEQ;
    const float* Bv = v + (size_t)(b * SEQ) * DIM + h * HD;
    float* C        = out + (size_t)(b * SEQ + i0) * DIM + h * HD;
    __shared__ __align__(16) float As[8][128];
    __shared__ __align__(16) float Bs[8][128];
    int t = threadIdx.x;
    int ar = t >> 1, ac = (t & 1) * 4;
    int br = t >> 5, bc = (t & 31) * 4;
    int ty = t >> 4, tx = t & 15;
    float acc[8][8];
    #pragma unroll
    for (int i = 0; i < 8; i++)
        #pragma unroll
        for (int j = 0; j < 8; j++) acc[i][j] = 0.f;

    int kend = i0 + 128;                    // probs are exactly 0 beyond the causal bound
    for (int k0 = 0; k0 < kend; k0 += 8) {
        float4 av = *(const float4*)(A + (size_t)(i0 + ar) * SEQ + k0 + ac);
        As[ac + 0][ar] = av.x; As[ac + 1][ar] = av.y;
        As[ac + 2][ar] = av.z; As[ac + 3][ar] = av.w;
        *(float4*)&Bs[br][bc] = *(const float4*)(Bv + (size_t)(k0 + br) * DIM + bc);
        __syncthreads();
        #pragma unroll
        for (int kk = 0; kk < 8; kk++) {
            float af[8], bf[8];
            *(float4*)&af[0] = *(const float4*)&As[kk][ty * 8];
            *(float4*)&af[4] = *(const float4*)&As[kk][ty * 8 + 4];
            *(float4*)&bf[0] = *(const float4*)&Bs[kk][tx * 8];
            *(float4*)&bf[4] = *(const float4*)&Bs[kk][tx * 8 + 4];
            #pragma unroll
            for (int i = 0; i < 8; i++)
                #pragma unroll
                for (int j = 0; j < 8; j++)
                    acc[i][j] += af[i] * bf[j];
        }
        __syncthreads();
    }
    #pragma unroll
    for (int i = 0; i < 8; i++)
        #pragma unroll
        for (int j = 0; j < 8; j++)
            C[(size_t)(ty * 8 + i) * DIM + tx * 8 + j] = acc[i][j];
}

// ---------------- SiLU(gate) * up, in place into gate ----------------
__global__ void silu_mul_kernel(float* __restrict__ g, const float* __restrict__ u) {
    size_t i = (size_t)blockIdx.x * blockDim.x + threadIdx.x;  // float4 index
    float4 gv = ((const float4*)g)[i];
    float4 uv = ((const float4*)u)[i];
    float4 o;
    o.x = gv.x / (1.f + expf(-gv.x)) * uv.x;
    o.y = gv.y / (1.f + expf(-gv.y)) * uv.y;
    o.z = gv.z / (1.f + expf(-gv.z)) * uv.z;
    o.w = gv.w / (1.f + expf(-gv.w)) * uv.w;
    ((float4*)g)[i] = o;
}

// ---------------- launch ----------------
extern "C" void kernel_launch(void* const* d_in, const int* in_sizes, int n_in,
                              void* d_out, int out_size) {
    const float* x           = (const float*)d_in[0];
    const float* mask        = (const float*)d_in[1];
    const float* w_attn_norm = (const float*)d_in[2];
    const float* wq          = (const float*)d_in[3];
    const float* wk          = (const float*)d_in[4];
    const float* wv          = (const float*)d_in[5];
    const float* wo          = (const float*)d_in[6];
    const float* w_ffn_norm  = (const float*)d_in[7];
    const float* wg          = (const float*)d_in[8];
    const float* wu          = (const float*)d_in[9];
    const float* wd          = (const float*)d_in[10];
    float* out = (float*)d_out;

    float *hn, *q, *k, *v, *ao, *h, *sc, *gate, *up;
    cudaGetSymbolAddress((void**)&hn,   g_hn);
    cudaGetSymbolAddress((void**)&q,    g_q);
    cudaGetSymbolAddress((void**)&k,    g_k);
    cudaGetSymbolAddress((void**)&v,    g_v);
    cudaGetSymbolAddress((void**)&ao,   g_ao);
    cudaGetSymbolAddress((void**)&h,    g_h);
    cudaGetSymbolAddress((void**)&sc,   g_scores);
    cudaGetSymbolAddress((void**)&gate, g_gate);
    cudaGetSymbolAddress((void**)&up,   g_up);

    // attn pre-norm
    rmsnorm_kernel<<<MROWS, 256>>>(x, w_attn_norm, hn);
    // QKV projections
    dim3 gqkv(DIM / 128, MROWS / 128);
    sgemm_kernel<<<gqkv, 256>>>(hn, wq, nullptr, q, MROWS, DIM, DIM, 0);
    sgemm_kernel<<<gqkv, 256>>>(hn, wk, nullptr, k, MROWS, DIM, DIM, 0);
    sgemm_kernel<<<gqkv, 256>>>(hn, wv, nullptr, v, MROWS, DIM, DIM, 0);
    // attention
    scores_kernel<<<dim3(SEQ / 64, SEQ / 64, BATCH * NHEADS), 256>>>(q, k, mask, sc);
    softmax_kernel<<<BATCH * NHEADS * SEQ, 128>>>(sc);
    av_kernel<<<dim3(1, SEQ / 128, BATCH * NHEADS), 256>>>(sc, v, ao);
    // O proj + residual -> h
    sgemm_kernel<<<gqkv, 256>>>(ao, wo, x, h, MROWS, DIM, DIM, 1);
    // ffn pre-norm
    rmsnorm_kernel<<<MROWS, 256>>>(h, w_ffn_norm, hn);
    // gate / up
    dim3 ggu(INTER / 128, MROWS / 128);
    sgemm_kernel<<<ggu, 256>>>(hn, wg, nullptr, gate, MROWS, INTER, DIM, 0);
    sgemm_kernel<<<ggu, 256>>>(hn, wu, nullptr, up,   MROWS, INTER, DIM, 0);
    // silu * up
    silu_mul_kernel<<<((size_t)MROWS * INTER / 4) / 256, 256>>>(gate, up);
    // down proj + residual -> out
    sgemm_kernel<<<gqkv, 256>>>(gate, wd, h, out, MROWS, DIM, INTER, 1);
}

// round 4
// speedup vs baseline: 3.7903x; 3.7882x over previous
#include <cuda_runtime.h>
#include <cstdint>
#include <math.h>

#define BATCH 2
#define SEQ 2048
#define DIM 2048
#define NHEADS 16
#define HD 128
#define INTER 8192
#define MROWS (BATCH*SEQ)
#define EPSF 1e-6f
#define NEGF -1e9f

// smem tile geometry (floats): A row stride 36 (pad 4), B row stride 136 (pad 8)
#define ASTR 36
#define BSTR 136
#define ASZ  (128*ASTR*4)        /* 18432 B */
#define BSZ  (32*BSTR*4)         /* 17408 B */
#define STAGE (ASZ + BSZ)        /* 35840 B */
#define SMEMDYN (2*STAGE)        /* 71680 B */

// ---------------- scratch (device globals: allocation-free) ----------------
__device__ float g_hn[(size_t)MROWS * DIM];
__device__ float g_q [(size_t)MROWS * DIM];
__device__ float g_kt[(size_t)MROWS * DIM];          // [bh][d][tok]
__device__ float g_v [(size_t)MROWS * DIM];
__device__ float g_ao[(size_t)MROWS * DIM];
__device__ float g_h [(size_t)MROWS * DIM];
__device__ float g_sc[(size_t)BATCH * NHEADS * SEQ * SEQ];
__device__ float g_gate[(size_t)MROWS * INTER];
__device__ float g_up  [(size_t)MROWS * INTER];
__device__ float g_wrq[(size_t)DIM * DIM];
__device__ float g_wrk[(size_t)DIM * DIM];
__device__ float g_wrv[(size_t)DIM * DIM];
__device__ float g_wro[(size_t)DIM * DIM];
__device__ float g_wrg[(size_t)DIM * INTER];
__device__ float g_wru[(size_t)DIM * INTER];
__device__ float g_wrd[(size_t)INTER * DIM];

// ---------------- helpers ----------------
__device__ __forceinline__ float rna_tf32(float x) {
    uint32_t u;
    asm("cvt.rna.tf32.f32 %0, %1;" : "=r"(u) : "f"(x));
    return __uint_as_float(u);
}
__device__ __forceinline__ uint32_t smem_u32(const void* p) {
    uint32_t a;
    asm("{ .reg .u64 t; cvta.to.shared.u64 t, %1; cvt.u32.u64 %0, t; }" : "=r"(a) : "l"(p));
    return a;
}
#define CP16(dst, src) \
    asm volatile("cp.async.cg.shared.global [%0], [%1], 16;" :: "r"(dst), "l"(src) : "memory")
#define CP_COMMIT() asm volatile("cp.async.commit_group;" ::: "memory")
#define CP_WAIT1()  asm volatile("cp.async.wait_group 1;" ::: "memory")

__device__ __forceinline__ void mma_tf32(float* d, const uint32_t* a, const uint32_t* b) {
    asm volatile("mma.sync.aligned.m16n8k8.row.col.f32.tf32.tf32.f32 "
        "{%0,%1,%2,%3}, {%4,%5,%6,%7}, {%8,%9}, {%0,%1,%2,%3};"
        : "+f"(d[0]), "+f"(d[1]), "+f"(d[2]), "+f"(d[3])
        : "r"(a[0]), "r"(a[1]), "r"(a[2]), "r"(a[3]), "r"(b[0]), "r"(b[1]));
}

// ---------------- tf32 mma GEMM: C[128,128] tile of A[M,K] @ B[K,N] ----------------
// EPI 0: plain (+res)  1: rna store  2: K-proj transposed rna store
//     3: scores (scale + causal)     4: AV (rna, causal K-trunc)
template<int EPI>
__global__ void __launch_bounds__(128, 2)
tc_gemm(const float* __restrict__ A0, const float* __restrict__ B0,
        const float* __restrict__ res, float* __restrict__ C,
        int lda, int ldb, int ldc, int K)
{
    extern __shared__ char dsm[];
    int tid = threadIdx.x;
    int wid = tid >> 5, lane = tid & 31;
    int gr = lane >> 2, cl = lane & 3;
    int warp_m = (wid >> 1) * 64, warp_n = (wid & 1) * 64;
    int bx = blockIdx.x, by = blockIdx.y;

    const float* Ap;
    const float* Bp;
    const float* Rp = nullptr;
    float* Cp = C;
    int row0 = 0, col0 = 0, i0 = 0, j0 = 0, kiters;

    if constexpr (EPI <= 2) {
        row0 = by * 128; col0 = bx * 128;
        Ap = A0 + (size_t)row0 * lda;
        Bp = B0 + col0;
        if constexpr (EPI != 2) {
            Cp = C + (size_t)row0 * ldc + col0;
            if (res) Rp = res + (size_t)row0 * ldc + col0;
        }
        kiters = K / 32;
    } else if constexpr (EPI == 3) {
        int bh = blockIdx.z; int b = bh >> 4, hh = bh & 15;
        i0 = by * 128; j0 = bx * 128;
        Cp = C + (size_t)bh * SEQ * SEQ + (size_t)i0 * SEQ + j0;
        if (j0 > i0) {                      // fully masked tile
            float4 n4 = make_float4(NEGF, NEGF, NEGF, NEGF);
            for (int e = tid; e < 128 * 32; e += 128)
                *(float4*)(Cp + (size_t)(e >> 5) * SEQ + (e & 31) * 4) = n4;
            return;
        }
        Ap = A0 + (size_t)(b * SEQ + i0) * DIM + hh * HD;     // Q
        Bp = B0 + (size_t)bh * HD * SEQ + j0;                 // Kt [d][tok]
        lda = DIM; ldb = SEQ;
        kiters = HD / 32;
    } else {                                // EPI 4: AV
        int bh = blockIdx.z; int b = bh >> 4, hh = bh & 15;
        i0 = by * 128;
        Ap = A0 + (size_t)bh * SEQ * SEQ + (size_t)i0 * SEQ;  // probs
        Bp = B0 + (size_t)(b * SEQ) * DIM + hh * HD;          // V [tok][d]
        Cp = C + (size_t)(b * SEQ + i0) * DIM + hh * HD;
        lda = SEQ; ldb = DIM; ldc = DIM;
        kiters = (i0 + 128) / 32;
    }

    float acc[4][8][4];
    #pragma unroll
    for (int mt = 0; mt < 4; mt++)
        #pragma unroll
        for (int nt = 0; nt < 8; nt++)
            #pragma unroll
            for (int e = 0; e < 4; e++) acc[mt][nt][e] = 0.f;

    uint32_t sbase = smem_u32(dsm);

    // ---- stage loader: A 128x32, B 32x128, 16 cp.async per thread ----
    auto load_stage = [&](int it, int buf) {
        uint32_t st = sbase + buf * STAGE;
        const float* ga = Ap + it * 32;
        const float* gb = Bp + (size_t)(it * 32) * ldb;
        #pragma unroll
        for (int i = 0; i < 8; i++) {
            int ch = tid + i * 128;
            int r = ch >> 3, j = ch & 7;
            CP16(st + (uint32_t)(r * (ASTR*4) + j * 16), ga + (size_t)r * lda + j * 4);
        }
        #pragma unroll
        for (int i = 0; i < 8; i++) {
            int ch = tid + i * 128;
            int r = ch >> 5, j = ch & 31;
            CP16(st + (uint32_t)(ASZ + r * (BSTR*4) + j * 16), gb + (size_t)r * ldb + j * 4);
        }
    };

    load_stage(0, 0);
    CP_COMMIT();

    for (int it = 0; it < kiters; ++it) {
        if (it + 1 < kiters) load_stage(it + 1, (it + 1) & 1);
        CP_COMMIT();
        CP_WAIT1();
        __syncthreads();

        const float* As = (const float*)(dsm + (it & 1) * STAGE);
        const float* Bs = (const float*)(dsm + (it & 1) * STAGE + ASZ);
        #pragma unroll
        for (int s = 0; s < 4; s++) {
            uint32_t bfr[8][2];
            #pragma unroll
            for (int nt = 0; nt < 8; nt++) {
                int bb = (s * 8 + cl) * BSTR + warp_n + nt * 8 + gr;
                bfr[nt][0] = __float_as_uint(Bs[bb]);
                bfr[nt][1] = __float_as_uint(Bs[bb + 4 * BSTR]);
            }
            #pragma unroll
            for (int mt = 0; mt < 4; mt++) {
                int ab = (warp_m + mt * 16 + gr) * ASTR + s * 8 + cl;
                uint32_t afr[4];
                afr[0] = __float_as_uint(As[ab]);
                afr[1] = __float_as_uint(As[ab + 8 * ASTR]);
                afr[2] = __float_as_uint(As[ab + 4]);
                afr[3] = __float_as_uint(As[ab + 8 * ASTR + 4]);
                #pragma unroll
                for (int nt = 0; nt < 8; nt++)
                    mma_tf32(acc[mt][nt], afr, bfr[nt]);
            }
        }
        __syncthreads();
    }

    // ---------------- epilogue ----------------
    #pragma unroll
    for (int mt = 0; mt < 4; mt++) {
        #pragma unroll
        for (int nt = 0; nt < 8; nt++) {
            int rl = warp_m + mt * 16 + gr;
            int ccl = warp_n + nt * 8 + 2 * cl;
            float v0 = acc[mt][nt][0], v1 = acc[mt][nt][1];
            float v2 = acc[mt][nt][2], v3 = acc[mt][nt][3];
            if constexpr (EPI == 0) {
                float* p0 = Cp + (size_t)rl * ldc + ccl;
                float* p1 = Cp + (size_t)(rl + 8) * ldc + ccl;
                if (Rp) {
                    float2 r0 = *(const float2*)(Rp + (size_t)rl * ldc + ccl);
                    float2 r1 = *(const float2*)(Rp + (size_t)(rl + 8) * ldc + ccl);
                    v0 += r0.x; v1 += r0.y; v2 += r1.x; v3 += r1.y;
                }
                *(float2*)p0 = make_float2(v0, v1);
                *(float2*)p1 = make_float2(v2, v3);
            } else if constexpr (EPI == 1 || EPI == 4) {
                float* p0 = Cp + (size_t)rl * ldc + ccl;
                float* p1 = Cp + (size_t)(rl + 8) * ldc + ccl;
                *(float2*)p0 = make_float2(rna_tf32(v0), rna_tf32(v1));
                *(float2*)p1 = make_float2(rna_tf32(v2), rna_tf32(v3));
            } else if constexpr (EPI == 2) {
                int n0 = col0 + ccl;
                int hh = n0 >> 7;
                #pragma unroll
                for (int e = 0; e < 4; e++) {
                    int mg = row0 + rl + (e >= 2 ? 8 : 0);
                    int n  = n0 + (e & 1);
                    int b = mg >> 11, tok = mg & (SEQ - 1);
                    int d = n & 127;
                    C[(((size_t)((b << 4) + hh) * HD + d) << 11) + tok] =
                        rna_tf32(acc[mt][nt][e]);
                }
            } else {  // EPI 3: scores
                const float scale = 0.08838834764831845f;  // 1/sqrt(128)
                int gi0 = i0 + rl, gi1 = gi0 + 8;
                int gj = j0 + ccl;
                float* p0 = Cp + (size_t)rl * SEQ + ccl;
                float* p1 = Cp + (size_t)(rl + 8) * SEQ + ccl;
                *(float2*)p0 = make_float2(gj     <= gi0 ? v0 * scale : NEGF,
                                           gj + 1 <= gi0 ? v1 * scale : NEGF);
                *(float2*)p1 = make_float2(gj     <= gi1 ? v2 * scale : NEGF,
                                           gj + 1 <= gi1 ? v3 * scale : NEGF);
            }
        }
    }
}

// ---------------- weight rna-round copy ----------------
__global__ void round_copy(const float* __restrict__ src, float* __restrict__ dst) {
    size_t i = (size_t)blockIdx.x * blockDim.x + threadIdx.x;
    float4 v = ((const float4*)src)[i];
    v.x = rna_tf32(v.x); v.y = rna_tf32(v.y);
    v.z = rna_tf32(v.z); v.w = rna_tf32(v.w);
    ((float4*)dst)[i] = v;
}

// ---------------- RMSNorm (rna output) ----------------
__global__ void rmsnorm_kernel(const float* __restrict__ x,
                               const float* __restrict__ w,
                               float* __restrict__ out) {
    int row = blockIdx.x;
    int t = threadIdx.x;                    // 256
    const float4* xr = (const float4*)(x + (size_t)row * DIM);
    const float4* wr = (const float4*)w;
    float4 a = xr[t];
    float4 b = xr[t + 256];
    float s = a.x*a.x + a.y*a.y + a.z*a.z + a.w*a.w
            + b.x*b.x + b.y*b.y + b.z*b.z + b.w*b.w;
    __shared__ float red[256];
    red[t] = s;
    __syncthreads();
    for (int off = 128; off > 0; off >>= 1) {
        if (t < off) red[t] += red[t + off];
        __syncthreads();
    }
    float inv = rsqrtf(red[0] * (1.0f / DIM) + EPSF);
    float4 wa = wr[t], wb = wr[t + 256];
    float4 oa, ob;
    oa.x = rna_tf32(a.x * inv * wa.x); oa.y = rna_tf32(a.y * inv * wa.y);
    oa.z = rna_tf32(a.z * inv * wa.z); oa.w = rna_tf32(a.w * inv * wa.w);
    ob.x = rna_tf32(b.x * inv * wb.x); ob.y = rna_tf32(b.y * inv * wb.y);
    ob.z = rna_tf32(b.z * inv * wb.z); ob.w = rna_tf32(b.w * inv * wb.w);
    float4* orow = (float4*)(out + (size_t)row * DIM);
    orow[t] = oa;
    orow[t + 256] = ob;
}

// ---------------- softmax over rows of 2048 (rna output) ----------------
__global__ void softmax_kernel(float* __restrict__ scores) {
    size_t row = blockIdx.x;
    float4* p = (float4*)(scores + row * (size_t)SEQ);
    int t = threadIdx.x;                    // 128
    float v[16];
    float m = -3.4e38f;
    #pragma unroll
    for (int i = 0; i < 4; i++) {
        float4 f = p[t + i * 128];
        v[i*4+0] = f.x; v[i*4+1] = f.y; v[i*4+2] = f.z; v[i*4+3] = f.w;
        m = fmaxf(m, fmaxf(fmaxf(f.x, f.y), fmaxf(f.z, f.w)));
    }
    __shared__ float red[128];
    red[t] = m;
    __syncthreads();
    for (int off = 64; off > 0; off >>= 1) {
        if (t < off) red[t] = fmaxf(red[t], red[t + off]);
        __syncthreads();
    }
    float rm = red[0];
    __syncthreads();
    float s = 0.f;
    #pragma unroll
    for (int i = 0; i < 16; i++) {
        v[i] = expf(v[i] - rm);
        s += v[i];
    }
    red[t] = s;
    __syncthreads();
    for (int off = 64; off > 0; off >>= 1) {
        if (t < off) red[t] += red[t + off];
        __syncthreads();
    }
    float inv = 1.0f / red[0];
    #pragma unroll
    for (int i = 0; i < 4; i++) {
        float4 f;
        f.x = rna_tf32(v[i*4+0] * inv); f.y = rna_tf32(v[i*4+1] * inv);
        f.z = rna_tf32(v[i*4+2] * inv); f.w = rna_tf32(v[i*4+3] * inv);
        p[t + i * 128] = f;
    }
}

// ---------------- SiLU(gate)*up (rna output, in place into gate) ----------------
__global__ void silu_mul_kernel(float* __restrict__ g, const float* __restrict__ u) {
    size_t i = (size_t)blockIdx.x * blockDim.x + threadIdx.x;
    float4 gv = ((const float4*)g)[i];
    float4 uv = ((const float4*)u)[i];
    float4 o;
    o.x = rna_tf32(gv.x / (1.f + expf(-gv.x)) * uv.x);
    o.y = rna_tf32(gv.y / (1.f + expf(-gv.y)) * uv.y);
    o.z = rna_tf32(gv.z / (1.f + expf(-gv.z)) * uv.z);
    o.w = rna_tf32(gv.w / (1.f + expf(-gv.w)) * uv.w);
    ((float4*)g)[i] = o;
}

// ---------------- host ----------------
extern "C" void kernel_launch(void* const* d_in, const int* in_sizes, int n_in,
                              void* d_out, int out_size) {
    const float* x           = (const float*)d_in[0];
    const float* w_attn_norm = (const float*)d_in[2];
    const float* wq          = (const float*)d_in[3];
    const float* wk          = (const float*)d_in[4];
    const float* wv          = (const float*)d_in[5];
    const float* wo          = (const float*)d_in[6];
    const float* w_ffn_norm  = (const float*)d_in[7];
    const float* wg          = (const float*)d_in[8];
    const float* wu          = (const float*)d_in[9];
    const float* wd          = (const float*)d_in[10];
    float* out = (float*)d_out;

    float *hn, *q, *kt, *v, *ao, *h, *sc, *gate, *up;
    float *wrq, *wrk, *wrv, *wro, *wrg, *wru, *wrd;
    cudaGetSymbolAddress((void**)&hn,   g_hn);
    cudaGetSymbolAddress((void**)&q,    g_q);
    cudaGetSymbolAddress((void**)&kt,   g_kt);
    cudaGetSymbolAddress((void**)&v,    g_v);
    cudaGetSymbolAddress((void**)&ao,   g_ao);
    cudaGetSymbolAddress((void**)&h,    g_h);
    cudaGetSymbolAddress((void**)&sc,   g_sc);
    cudaGetSymbolAddress((void**)&gate, g_gate);
    cudaGetSymbolAddress((void**)&up,   g_up);
    cudaGetSymbolAddress((void**)&wrq,  g_wrq);
    cudaGetSymbolAddress((void**)&wrk,  g_wrk);
    cudaGetSymbolAddress((void**)&wrv,  g_wrv);
    cudaGetSymbolAddress((void**)&wro,  g_wro);
    cudaGetSymbolAddress((void**)&wrg,  g_wrg);
    cudaGetSymbolAddress((void**)&wru,  g_wru);
    cudaGetSymbolAddress((void**)&wrd,  g_wrd);

    cudaFuncSetAttribute(tc_gemm<0>, cudaFuncAttributeMaxDynamicSharedMemorySize, SMEMDYN);
    cudaFuncSetAttribute(tc_gemm<1>, cudaFuncAttributeMaxDynamicSharedMemorySize, SMEMDYN);
    cudaFuncSetAttribute(tc_gemm<2>, cudaFuncAttributeMaxDynamicSharedMemorySize, SMEMDYN);
    cudaFuncSetAttribute(tc_gemm<3>, cudaFuncAttributeMaxDynamicSharedMemorySize, SMEMDYN);
    cudaFuncSetAttribute(tc_gemm<4>, cudaFuncAttributeMaxDynamicSharedMemorySize, SMEMDYN);

    // weight pre-rounding (rna to tf32 grid)
    round_copy<<<(DIM*DIM/4)/256,   256>>>(wq, wrq);
    round_copy<<<(DIM*DIM/4)/256,   256>>>(wk, wrk);
    round_copy<<<(DIM*DIM/4)/256,   256>>>(wv, wrv);
    round_copy<<<(DIM*DIM/4)/256,   256>>>(wo, wro);
    round_copy<<<(DIM*INTER/4)/256, 256>>>(wg, wrg);
    round_copy<<<(DIM*INTER/4)/256, 256>>>(wu, wru);
    round_copy<<<(DIM*INTER/4)/256, 256>>>(wd, wrd);

    // attn pre-norm
    rmsnorm_kernel<<<MROWS, 256>>>(x, w_attn_norm, hn);
    // projections (A = hn rna'd, B = rounded weights [K,N])
    dim3 gpr(DIM/128, MROWS/128);
    tc_gemm<1><<<gpr, 128, SMEMDYN>>>(hn, wrq, nullptr, q,  DIM, DIM, DIM, DIM);
    tc_gemm<2><<<gpr, 128, SMEMDYN>>>(hn, wrk, nullptr, kt, DIM, DIM, DIM, DIM);
    tc_gemm<1><<<gpr, 128, SMEMDYN>>>(hn, wrv, nullptr, v,  DIM, DIM, DIM, DIM);
    // attention
    tc_gemm<3><<<dim3(SEQ/128, SEQ/128, BATCH*NHEADS), 128, SMEMDYN>>>(q, kt, nullptr, sc, 0, 0, SEQ, HD);
    softmax_kernel<<<BATCH*NHEADS*SEQ, 128>>>(sc);
    tc_gemm<4><<<dim3(1, SEQ/128, BATCH*NHEADS), 128, SMEMDYN>>>(sc, v, nullptr, ao, 0, 0, DIM, SEQ);
    // O proj + residual
    tc_gemm<0><<<gpr, 128, SMEMDYN>>>(ao, wro, x, h, DIM, DIM, DIM, DIM);
    // ffn
    rmsnorm_kernel<<<MROWS, 256>>>(h, w_ffn_norm, hn);
    dim3 ggu(INTER/128, MROWS/128);
    tc_gemm<0><<<ggu, 128, SMEMDYN>>>(hn, wrg, nullptr, gate, DIM, INTER, INTER, DIM);
    tc_gemm<0><<<ggu, 128, SMEMDYN>>>(hn, wru, nullptr, up,   DIM, INTER, INTER, DIM);
    silu_mul_kernel<<<((size_t)MROWS*INTER/4)/256, 256>>>(gate, up);
    // down proj + residual
    tc_gemm<0><<<gpr, 128, SMEMDYN>>>(gate, wrd, h, out, INTER, DIM, DIM, INTER);
}